// round 2
// baseline (speedup 1.0000x reference)
#include <cuda_runtime.h>

#define Bb 4
#define Nn 1024
#define BN 4096
#define Ff 128
#define Rr 16
#define Ee 65536
#define NSTEPS 2

// ---------------- scratch (device globals; no runtime allocation) ----------------
__device__ float g_agg1[2][BN * Ff];           // psi1 neighbor aggregation (s, t)
__device__ float g_h[2][BN * Ff];              // h_s, h_t
__device__ float g_Shat[(size_t)Bb * Nn * Nn]; // 16 MB logits
__device__ float g_m[BN];                      // row max
__device__ float g_invZ[BN];                   // 1/row sum-exp
__device__ float g_rt[BN * Rr];                // r_t
__device__ float g_aggR[BN * Rr];              // psi2 aggregation scratch
__device__ float g_As[NSTEPS][BN * Rr];        // A_s = o_s@Wm1 + bm1 per step
__device__ float g_Bt[BN * Rr];                // B_t = o_t@Wm1

__device__ __forceinline__ void red_add_f4(float* p, float4 v) {
    asm volatile("red.global.add.v4.f32 [%0], {%1,%2,%3,%4};"
                 :: "l"(p), "f"(v.x), "f"(v.y), "f"(v.z), "f"(v.w) : "memory");
}

// ---------------- zero kernels ----------------
__global__ void k_zero_agg1() {
    int i = blockIdx.x * blockDim.x + threadIdx.x;      // 262144 float4
    ((float4*)g_agg1)[i] = make_float4(0.f, 0.f, 0.f, 0.f);
}

__global__ void k_zeroR(int which) {                    // 16384 float4
    float* p = which ? g_rt : g_aggR;
    int i = blockIdx.x * blockDim.x + threadIdx.x;
    ((float4*)p)[i] = make_float4(0.f, 0.f, 0.f, 0.f);
}

// ---------------- psi1 aggregation: agg[dst] += x[src] (vector red) ----------------
// one warp per edge: 32 lanes x float4 = 128 floats
__global__ void k_scatter128(const float* __restrict__ xs, const float* __restrict__ xt,
                             const int* __restrict__ eis, const int* __restrict__ eit) {
    int g = blockIdx.y;
    const float* x = g ? xt : xs;
    const int* ei = g ? eit : eis;
    float* agg = g_agg1[g];
    int idx = blockIdx.x * blockDim.x + threadIdx.x;    // < E*32
    int e = idx >> 5;
    int q = idx & 31;
    int src = ei[e];
    int dst = ei[Ee + e];
    float4 v = *(const float4*)&x[(size_t)src * Ff + 4 * q];
    red_add_f4(&agg[(size_t)dst * Ff + 4 * q], v);
}

// ---------------- psi1 GEMM: h = relu(x@Ws + agg@Wn + b1) ----------------
// BM=64, BN=128, K=256 (two phases of 128); 256 threads; micro 4x8
__global__ __launch_bounds__(256) void k_psi1(
    const float* __restrict__ xs, const float* __restrict__ xt,
    const float* __restrict__ Ws, const float* __restrict__ Wn,
    const float* __restrict__ bias) {
    __shared__ float sA[16][68];     // k-major, padded
    __shared__ float sW[16][128];

    int g = blockIdx.y;
    const float* x = g ? xt : xs;
    const float* agg = g_agg1[g];
    float* h = g_h[g];
    int row0 = blockIdx.x * 64;

    int tid = threadIdx.x;
    int tx = tid & 15;          // output cols 4*tx, 4*tx+64
    int ty = tid >> 4;          // output rows 4*ty..4*ty+3
    int lr = tid & 63;          // A-load row
    int lk = (tid >> 6) * 4;    // A-load k offset
    int wr = tid >> 4;          // W-load row (0..15)
    int wc = 8 * (tid & 15);    // W-load col

    float acc[4][8];
#pragma unroll
    for (int i = 0; i < 4; ++i)
#pragma unroll
        for (int j = 0; j < 8; ++j) acc[i][j] = 0.f;

    for (int kc = 0; kc < 256; kc += 16) {
        const float* A = (kc < 128) ? x : agg;
        const float* W = (kc < 128) ? Ws : Wn;
        int kcol = kc & 127;
        float4 av = *(const float4*)&A[(size_t)(row0 + lr) * Ff + kcol + lk];
        float4 w0 = *(const float4*)&W[(size_t)(kcol + wr) * Ff + wc];
        float4 w1 = *(const float4*)&W[(size_t)(kcol + wr) * Ff + wc + 4];
        __syncthreads();
        sA[lk + 0][lr] = av.x;
        sA[lk + 1][lr] = av.y;
        sA[lk + 2][lr] = av.z;
        sA[lk + 3][lr] = av.w;
        *(float4*)&sW[wr][wc] = w0;
        *(float4*)&sW[wr][wc + 4] = w1;
        __syncthreads();
#pragma unroll
        for (int k = 0; k < 16; ++k) {
            float4 a = *(float4*)&sA[k][4 * ty];
            float4 b0 = *(float4*)&sW[k][4 * tx];
            float4 b1 = *(float4*)&sW[k][4 * tx + 64];
            float ar[4] = {a.x, a.y, a.z, a.w};
#pragma unroll
            for (int i = 0; i < 4; ++i) {
                acc[i][0] += ar[i] * b0.x; acc[i][1] += ar[i] * b0.y;
                acc[i][2] += ar[i] * b0.z; acc[i][3] += ar[i] * b0.w;
                acc[i][4] += ar[i] * b1.x; acc[i][5] += ar[i] * b1.y;
                acc[i][6] += ar[i] * b1.z; acc[i][7] += ar[i] * b1.w;
            }
        }
    }
    float4 bv0 = *(const float4*)&bias[4 * tx];
    float4 bv1 = *(const float4*)&bias[4 * tx + 64];
#pragma unroll
    for (int i = 0; i < 4; ++i) {
        int row = row0 + 4 * ty + i;
        float4 o0, o1;
        o0.x = fmaxf(acc[i][0] + bv0.x, 0.f);
        o0.y = fmaxf(acc[i][1] + bv0.y, 0.f);
        o0.z = fmaxf(acc[i][2] + bv0.z, 0.f);
        o0.w = fmaxf(acc[i][3] + bv0.w, 0.f);
        o1.x = fmaxf(acc[i][4] + bv1.x, 0.f);
        o1.y = fmaxf(acc[i][5] + bv1.y, 0.f);
        o1.z = fmaxf(acc[i][6] + bv1.z, 0.f);
        o1.w = fmaxf(acc[i][7] + bv1.w, 0.f);
        *(float4*)&h[(size_t)row * Ff + 4 * tx] = o0;
        *(float4*)&h[(size_t)row * Ff + 4 * tx + 64] = o1;
    }
}

// ---------------- S_hat = h_s @ h_t^T per batch ----------------
// BM=BN=128, BK=16; 256 threads; 8x8 microtile; k-major smem
__global__ __launch_bounds__(256) void k_shat() {
    __shared__ float sA[16][132];
    __shared__ float sB[16][132];

    int b = blockIdx.z;
    int t0 = blockIdx.x * 128;
    int s0 = blockIdx.y * 128;
    const float* hs = g_h[0] + (size_t)b * Nn * Ff;
    const float* ht = g_h[1] + (size_t)b * Nn * Ff;

    int tid = threadIdx.x;
    int tx = tid & 15;
    int ty = tid >> 4;
    int lr = tid & 127;
    int lk = (tid >> 7) * 8;

    float acc[8][8];
#pragma unroll
    for (int i = 0; i < 8; ++i)
#pragma unroll
        for (int j = 0; j < 8; ++j) acc[i][j] = 0.f;

    for (int kc = 0; kc < Ff; kc += 16) {
        float4 a0 = *(const float4*)&hs[(size_t)(s0 + lr) * Ff + kc + lk];
        float4 a1 = *(const float4*)&hs[(size_t)(s0 + lr) * Ff + kc + lk + 4];
        float4 c0 = *(const float4*)&ht[(size_t)(t0 + lr) * Ff + kc + lk];
        float4 c1 = *(const float4*)&ht[(size_t)(t0 + lr) * Ff + kc + lk + 4];
        __syncthreads();
        sA[lk + 0][lr] = a0.x; sA[lk + 1][lr] = a0.y; sA[lk + 2][lr] = a0.z; sA[lk + 3][lr] = a0.w;
        sA[lk + 4][lr] = a1.x; sA[lk + 5][lr] = a1.y; sA[lk + 6][lr] = a1.z; sA[lk + 7][lr] = a1.w;
        sB[lk + 0][lr] = c0.x; sB[lk + 1][lr] = c0.y; sB[lk + 2][lr] = c0.z; sB[lk + 3][lr] = c0.w;
        sB[lk + 4][lr] = c1.x; sB[lk + 5][lr] = c1.y; sB[lk + 6][lr] = c1.z; sB[lk + 7][lr] = c1.w;
        __syncthreads();
#pragma unroll
        for (int k = 0; k < 16; ++k) {
            float4 a0v = *(float4*)&sA[k][4 * ty];
            float4 a1v = *(float4*)&sA[k][4 * ty + 64];
            float4 b0v = *(float4*)&sB[k][4 * tx];
            float4 b1v = *(float4*)&sB[k][4 * tx + 64];
            float ar[8] = {a0v.x, a0v.y, a0v.z, a0v.w, a1v.x, a1v.y, a1v.z, a1v.w};
            float br[8] = {b0v.x, b0v.y, b0v.z, b0v.w, b1v.x, b1v.y, b1v.z, b1v.w};
#pragma unroll
            for (int i = 0; i < 8; ++i)
#pragma unroll
                for (int j = 0; j < 8; ++j) acc[i][j] += ar[i] * br[j];
        }
    }
#pragma unroll
    for (int i = 0; i < 8; ++i) {
        int row = s0 + ((i < 4) ? (4 * ty + i) : (64 + 4 * ty + i - 4));
        float* dst = g_Shat + ((size_t)(b * Nn + row)) * Nn + t0;
        float4 o0 = make_float4(acc[i][0], acc[i][1], acc[i][2], acc[i][3]);
        float4 o1 = make_float4(acc[i][4], acc[i][5], acc[i][6], acc[i][7]);
        *(float4*)&dst[4 * tx] = o0;
        *(float4*)&dst[4 * tx + 64] = o1;
    }
}

// ---------------- row stats: m, 1/Z ----------------
__global__ __launch_bounds__(256) void k_stats() {
    int row = blockIdx.x;
    int tid = threadIdx.x;
    const float4* p = (const float4*)(g_Shat + (size_t)row * Nn);
    float4 v = p[tid];
    float m = fmaxf(fmaxf(v.x, v.y), fmaxf(v.z, v.w));
#pragma unroll
    for (int o = 16; o > 0; o >>= 1) m = fmaxf(m, __shfl_xor_sync(0xffffffffu, m, o));
    __shared__ float smax[8];
    __shared__ float ssum[8];
    int wid = tid >> 5, lane = tid & 31;
    if (lane == 0) smax[wid] = m;
    __syncthreads();
    if (tid == 0) {
        float mm = smax[0];
#pragma unroll
        for (int i = 1; i < 8; ++i) mm = fmaxf(mm, smax[i]);
        smax[0] = mm;
    }
    __syncthreads();
    m = smax[0];
    float s = __expf(v.x - m) + __expf(v.y - m) + __expf(v.z - m) + __expf(v.w - m);
#pragma unroll
    for (int o = 16; o > 0; o >>= 1) s += __shfl_xor_sync(0xffffffffu, s, o);
    if (lane == 0) ssum[wid] = s;
    __syncthreads();
    if (tid == 0) {
        float ss = 0.f;
#pragma unroll
        for (int i = 0; i < 8; ++i) ss += ssum[i];
        g_m[row] = m;
        g_invZ[row] = 1.0f / ss;
    }
}

// ---------------- softmax write-out ----------------
__global__ __launch_bounds__(256) void k_smout(float* __restrict__ out) {
    size_t i4 = (size_t)blockIdx.x * blockDim.x + threadIdx.x;  // over 1M float4
    float4 v = ((const float4*)g_Shat)[i4];
    int row = (int)(i4 >> 8);
    float m = g_m[row], iz = g_invZ[row];
    float4 o;
    o.x = __expf(v.x - m) * iz;
    o.y = __expf(v.y - m) * iz;
    o.z = __expf(v.z - m) * iz;
    o.w = __expf(v.w - m) * iz;
    ((float4*)out)[i4] = o;
}

// ---------------- r_t = softmax(S_hat)^T @ r_s ----------------
__global__ __launch_bounds__(128) void k_rt(const float* __restrict__ rs) {
    __shared__ float s_rs[128][Rr];
    __shared__ float s_m[128];
    __shared__ float s_iz[128];
    int b = blockIdx.z;
    int t0 = blockIdx.x * 128;
    int s0 = blockIdx.y * 128;
    int tid = threadIdx.x;
#pragma unroll
    for (int i = 0; i < 16; ++i) {
        int lin = tid + 128 * i;
        int r = lin >> 4, c = lin & 15;
        s_rs[r][c] = rs[((size_t)(b * Nn + s0 + r)) * Rr + c];
    }
    s_m[tid] = g_m[b * Nn + s0 + tid];
    s_iz[tid] = g_invZ[b * Nn + s0 + tid];
    __syncthreads();

    int t = t0 + tid;
    float acc[Rr];
#pragma unroll
    for (int r = 0; r < Rr; ++r) acc[r] = 0.f;
    const float* sp = g_Shat + ((size_t)(b * Nn + s0)) * Nn + t;
#pragma unroll 4
    for (int s = 0; s < 128; ++s) {
        float w = __expf(sp[(size_t)s * Nn] - s_m[s]) * s_iz[s];
#pragma unroll
        for (int r = 0; r < Rr; ++r) acc[r] += w * s_rs[s][r];
    }
    float* rt = g_rt + (size_t)(b * Nn + t) * Rr;
#pragma unroll
    for (int q = 0; q < 4; ++q)
        red_add_f4(&rt[4 * q], make_float4(acc[4 * q], acc[4 * q + 1], acc[4 * q + 2], acc[4 * q + 3]));
}

// ---------------- psi2 aggregation (R=16, vector red) ----------------
__global__ void k_scatter16(int src_is_rt, const float* __restrict__ rext,
                            const int* __restrict__ ei) {
    int idx = blockIdx.x * blockDim.x + threadIdx.x;   // < E*4
    int e = idx >> 2;
    int q = idx & 3;
    const float* src = src_is_rt ? g_rt : rext;
    float4 v = *(const float4*)&src[(size_t)ei[e] * Rr + 4 * q];
    red_add_f4(&g_aggR[(size_t)ei[Ee + e] * Rr + 4 * q], v);
}

// ---------------- psi2 + Wm1 projection fused ----------------
__global__ __launch_bounds__(256) void k_psi2(
    int src_is_rt, const float* __restrict__ rext,
    const float* __restrict__ W2s, const float* __restrict__ W2n,
    const float* __restrict__ b2v, const float* __restrict__ Wm1,
    int use_bm1, const float* __restrict__ bm1v, int out_is_B, int step) {
    __shared__ float sr[16][17], sg[16][17], so[16][17];
    __shared__ float sWs[256], sWn[256], sWm[256];
    int tid = threadIdx.x;
    int r = tid >> 4, j = tid & 15;
    int row0 = blockIdx.x * 16;
    const float* src = src_is_rt ? g_rt : rext;
    sr[r][j] = src[(size_t)(row0 + r) * Rr + j];
    sg[r][j] = g_aggR[(size_t)(row0 + r) * Rr + j];
    sWs[tid] = W2s[tid];
    sWn[tid] = W2n[tid];
    sWm[tid] = Wm1[tid];
    __syncthreads();
    float acc = b2v[j];
#pragma unroll
    for (int k = 0; k < 16; ++k)
        acc += sr[r][k] * sWs[k * 16 + j] + sg[r][k] * sWn[k * 16 + j];
    so[r][j] = fmaxf(acc, 0.f);
    __syncthreads();
    float a2 = use_bm1 ? bm1v[j] : 0.f;
#pragma unroll
    for (int k = 0; k < 16; ++k) a2 += so[r][k] * sWm[k * 16 + j];
    float* dst = out_is_B ? g_Bt : g_As[step];
    dst[(size_t)(row0 + r) * Rr + j] = a2;
}

// ---------------- S_hat += sum_k relu(A_s[s,k]-B_t[t,k])*Wm2[k] + bm2 ----------------
__global__ __launch_bounds__(256) void k_upd(int step, const float* __restrict__ Wm2,
                                             const float* __restrict__ bm2v) {
    __shared__ float sA[16][16];
    __shared__ float swm[16];
    int b = blockIdx.z;
    int s0 = blockIdx.y * 16;
    int t0 = blockIdx.x * 256;
    int tid = threadIdx.x;
    sA[tid >> 4][tid & 15] = g_As[step][(size_t)(b * Nn + s0 + (tid >> 4)) * Rr + (tid & 15)];
    if (tid < 16) swm[tid] = Wm2[tid];
    float bb = bm2v[0];
    int t = t0 + tid;
    float Bk[16];
    const float4* bp = (const float4*)&g_Bt[(size_t)(b * Nn + t) * Rr];
    float4 b0 = bp[0], b1 = bp[1], b2 = bp[2], b3 = bp[3];
    Bk[0] = b0.x; Bk[1] = b0.y; Bk[2] = b0.z; Bk[3] = b0.w;
    Bk[4] = b1.x; Bk[5] = b1.y; Bk[6] = b1.z; Bk[7] = b1.w;
    Bk[8] = b2.x; Bk[9] = b2.y; Bk[10] = b2.z; Bk[11] = b2.w;
    Bk[12] = b3.x; Bk[13] = b3.y; Bk[14] = b3.z; Bk[15] = b3.w;
    __syncthreads();
    float* shp = g_Shat + ((size_t)(b * Nn + s0)) * Nn + t;
#pragma unroll
    for (int s = 0; s < 16; ++s) {
        float acc = bb;
#pragma unroll
        for (int k = 0; k < 16; ++k)
            acc += fmaxf(sA[s][k] - Bk[k], 0.f) * swm[k];
        shp[(size_t)s * Nn] += acc;
    }
}

// ---------------- host orchestration ----------------
extern "C" void kernel_launch(void* const* d_in, const int* in_sizes, int n_in,
                              void* d_out, int out_size) {
    const float* x_s   = (const float*)d_in[0];
    const int*   ei_s  = (const int*)d_in[1];
    const float* x_t   = (const float*)d_in[2];
    const int*   ei_t  = (const int*)d_in[3];
    const float* W1s   = (const float*)d_in[4];
    const float* W1n   = (const float*)d_in[5];
    const float* b1    = (const float*)d_in[6];
    const float* W2s   = (const float*)d_in[7];
    const float* W2n   = (const float*)d_in[8];
    const float* b2v   = (const float*)d_in[9];
    const float* Wm1   = (const float*)d_in[10];
    const float* bm1v  = (const float*)d_in[11];
    const float* Wm2   = (const float*)d_in[12];
    const float* bm2v  = (const float*)d_in[13];
    const float* rsteps = (const float*)d_in[14];
    float* out = (float*)d_out;

    // psi1
    k_zero_agg1<<<1024, 256>>>();
    k_scatter128<<<dim3(Ee * 32 / 256, 2), 256>>>(x_s, x_t, ei_s, ei_t);
    k_psi1<<<dim3(BN / 64, 2), 256>>>(x_s, x_t, W1s, W1n, b1);

    // S_hat + initial stats + S_0
    k_shat<<<dim3(Nn / 128, Nn / 128, Bb), 256>>>();
    k_stats<<<BN, 256>>>();
    k_smout<<<4096, 256>>>(out);

    for (int step = 0; step < NSTEPS; ++step) {
        const float* rs = rsteps + (size_t)step * Bb * Nn * Rr;

        // o_s path -> A_s[step]
        k_zeroR<<<64, 256>>>(0);
        k_scatter16<<<Ee * 4 / 256, 256>>>(0, rs, ei_s);
        k_psi2<<<BN / 16, 256>>>(0, rs, W2s, W2n, b2v, Wm1, 1, bm1v, 0, step);

        // r_t = softmax(S_hat)^T @ r_s
        k_zeroR<<<64, 256>>>(1);
        k_rt<<<dim3(8, 8, Bb), 128>>>(rs);

        // o_t path -> B_t
        k_zeroR<<<64, 256>>>(0);
        k_scatter16<<<Ee * 4 / 256, 256>>>(1, rs, ei_t);
        k_psi2<<<BN / 16, 256>>>(1, rs, W2s, W2n, b2v, Wm1, 0, bm1v, 1, step);

        // S_hat += upd ; refresh stats
        k_upd<<<dim3(4, 64, Bb), 256>>>(step, Wm2, bm2v);
        k_stats<<<BN, 256>>>();
    }

    // S_L
    k_smout<<<4096, 256>>>(out + (size_t)Bb * Nn * Nn);
}

// round 4
// speedup vs baseline: 1.5016x; 1.5016x over previous
#include <cuda_runtime.h>

#define Bb 4
#define Nn 1024
#define BN 4096
#define Ff 128
#define Rr 16
#define Ee 65536
#define NSTEPS 2

// ---------------- scratch (device globals; no runtime allocation) ----------------
__device__ float g_agg1[2][BN * Ff];           // psi1 neighbor aggregation (s, t)
__device__ float g_h[2][BN * Ff];              // h_s, h_t
__device__ float g_Shat[(size_t)Bb * Nn * Nn]; // 16 MB logits
__device__ float g_m[BN];                      // row max
__device__ float g_invZ[BN];                   // 1/row sum-exp
__device__ float g_rt[BN * Rr];                // r_t
__device__ float g_aggR[BN * Rr];              // psi2 aggregation scratch
__device__ float g_As[NSTEPS][BN * Rr];        // A_s = o_s@Wm1 + bm1 per step
__device__ float g_Bt[BN * Rr];                // B_t = o_t@Wm1

__device__ __forceinline__ void red_add_f4(float* p, float4 v) {
    asm volatile("red.global.add.v4.f32 [%0], {%1,%2,%3,%4};"
                 :: "l"(p), "f"(v.x), "f"(v.y), "f"(v.z), "f"(v.w) : "memory");
}

// ---------------- zero kernels ----------------
__global__ void k_zero_agg1() {
    int i = blockIdx.x * blockDim.x + threadIdx.x;      // 262144 float4
    ((float4*)g_agg1)[i] = make_float4(0.f, 0.f, 0.f, 0.f);
}

__global__ void k_zeroR(int which) {                    // 16384 float4
    float* p = which ? g_rt : g_aggR;
    int i = blockIdx.x * blockDim.x + threadIdx.x;
    ((float4*)p)[i] = make_float4(0.f, 0.f, 0.f, 0.f);
}

// ---------------- psi1 aggregation: agg[dst] += x[src] (vector red) ----------------
__global__ void k_scatter128(const float* __restrict__ xs, const float* __restrict__ xt,
                             const int* __restrict__ eis, const int* __restrict__ eit) {
    int g = blockIdx.y;
    const float* x = g ? xt : xs;
    const int* ei = g ? eit : eis;
    float* agg = g_agg1[g];
    int idx = blockIdx.x * blockDim.x + threadIdx.x;    // < E*32
    int e = idx >> 5;
    int q = idx & 31;
    int src = ei[e];
    int dst = ei[Ee + e];
    float4 v = *(const float4*)&x[(size_t)src * Ff + 4 * q];
    red_add_f4(&agg[(size_t)dst * Ff + 4 * q], v);
}

// ---------------- psi1 GEMM: h = relu(x@Ws + agg@Wn + b1) ----------------
// BM=64, BN=64, K=256 (x||agg phases); 256 threads; 4x4 micro; double-buffered
__global__ __launch_bounds__(256) void k_psi1(
    const float* __restrict__ xs, const float* __restrict__ xt,
    const float* __restrict__ Ws, const float* __restrict__ Wn,
    const float* __restrict__ bias) {
    __shared__ float sA[2][16][68];
    __shared__ float sW[2][16][68];

    int g = blockIdx.z;
    int c0 = blockIdx.y * 64;
    int row0 = blockIdx.x * 64;
    const float* x = g ? xt : xs;
    const float* agg = g_agg1[g];
    float* h = g_h[g];

    int tid = threadIdx.x;
    int tx = tid & 15, ty = tid >> 4;
    int ar_ = tid & 63, ak = (tid >> 6) * 4;
    int wr = tid >> 4, wc = 4 * (tid & 15);

    float acc[4][4];
#pragma unroll
    for (int i = 0; i < 4; ++i)
#pragma unroll
        for (int j = 0; j < 4; ++j) acc[i][j] = 0.f;

#define LOAD_A(c) (*(const float4*)&(((c) < 8) ? x : agg)[(size_t)(row0 + ar_) * Ff + (((c)*16) & 127) + ak])
#define LOAD_W(c) (*(const float4*)&(((c) < 8) ? Ws : Wn)[(size_t)((((c)*16) & 127) + wr) * Ff + c0 + wc])

    float4 va = LOAD_A(0);
    float4 vw = LOAD_W(0);
    sA[0][ak + 0][ar_] = va.x; sA[0][ak + 1][ar_] = va.y;
    sA[0][ak + 2][ar_] = va.z; sA[0][ak + 3][ar_] = va.w;
    *(float4*)&sW[0][wr][wc] = vw;
    va = LOAD_A(1);
    vw = LOAD_W(1);
    __syncthreads();

    for (int c = 0; c < 16; ++c) {
        int cur = c & 1;
        if (c < 15) {
            int nxt = cur ^ 1;
            sA[nxt][ak + 0][ar_] = va.x; sA[nxt][ak + 1][ar_] = va.y;
            sA[nxt][ak + 2][ar_] = va.z; sA[nxt][ak + 3][ar_] = va.w;
            *(float4*)&sW[nxt][wr][wc] = vw;
        }
        if (c < 14) {
            va = LOAD_A(c + 2);
            vw = LOAD_W(c + 2);
        }
#pragma unroll
        for (int k = 0; k < 16; ++k) {
            float4 a = *(float4*)&sA[cur][k][4 * ty];
            float4 w = *(float4*)&sW[cur][k][4 * tx];
            float arr[4] = {a.x, a.y, a.z, a.w};
#pragma unroll
            for (int i = 0; i < 4; ++i) {
                acc[i][0] += arr[i] * w.x; acc[i][1] += arr[i] * w.y;
                acc[i][2] += arr[i] * w.z; acc[i][3] += arr[i] * w.w;
            }
        }
        __syncthreads();
    }
#undef LOAD_A
#undef LOAD_W

    float4 bv = *(const float4*)&bias[c0 + 4 * tx];
#pragma unroll
    for (int i = 0; i < 4; ++i) {
        int row = row0 + 4 * ty + i;
        float4 o;
        o.x = fmaxf(acc[i][0] + bv.x, 0.f);
        o.y = fmaxf(acc[i][1] + bv.y, 0.f);
        o.z = fmaxf(acc[i][2] + bv.z, 0.f);
        o.w = fmaxf(acc[i][3] + bv.w, 0.f);
        *(float4*)&h[(size_t)row * Ff + c0 + 4 * tx] = o;
    }
}

// ---------------- S_hat = h_s @ h_t^T per batch ----------------
// BM=BN=128, BK=8; 256 threads; 8x8 micro; double-buffered, 1 sync/chunk
__global__ __launch_bounds__(256, 2) void k_shat() {
    __shared__ float sA[2][8][132];
    __shared__ float sB[2][8][132];

    int b = blockIdx.z;
    int t0 = blockIdx.x * 128;
    int s0 = blockIdx.y * 128;
    const float* hs = g_h[0] + (size_t)b * Nn * Ff;
    const float* ht = g_h[1] + (size_t)b * Nn * Ff;

    int tid = threadIdx.x;
    int tx = tid & 15;
    int ty = tid >> 4;
    int lr = tid & 127;
    int lk = (tid >> 7) * 4;    // 0 or 4

    const float* pa = &hs[(size_t)(s0 + lr) * Ff + lk];
    const float* pb = &ht[(size_t)(t0 + lr) * Ff + lk];

    float acc[8][8];
#pragma unroll
    for (int i = 0; i < 8; ++i)
#pragma unroll
        for (int j = 0; j < 8; ++j) acc[i][j] = 0.f;

    float4 ra = *(const float4*)pa;
    float4 rb = *(const float4*)pb;
    sA[0][lk + 0][lr] = ra.x; sA[0][lk + 1][lr] = ra.y;
    sA[0][lk + 2][lr] = ra.z; sA[0][lk + 3][lr] = ra.w;
    sB[0][lk + 0][lr] = rb.x; sB[0][lk + 1][lr] = rb.y;
    sB[0][lk + 2][lr] = rb.z; sB[0][lk + 3][lr] = rb.w;
    ra = *(const float4*)(pa + 8);
    rb = *(const float4*)(pb + 8);
    __syncthreads();

    for (int c = 0; c < 16; ++c) {
        int cur = c & 1;
        if (c < 15) {
            int nxt = cur ^ 1;
            sA[nxt][lk + 0][lr] = ra.x; sA[nxt][lk + 1][lr] = ra.y;
            sA[nxt][lk + 2][lr] = ra.z; sA[nxt][lk + 3][lr] = ra.w;
            sB[nxt][lk + 0][lr] = rb.x; sB[nxt][lk + 1][lr] = rb.y;
            sB[nxt][lk + 2][lr] = rb.z; sB[nxt][lk + 3][lr] = rb.w;
        }
        if (c < 14) {
            ra = *(const float4*)(pa + 8 * (c + 2));
            rb = *(const float4*)(pb + 8 * (c + 2));
        }
#pragma unroll
        for (int k = 0; k < 8; ++k) {
            float4 a0v = *(float4*)&sA[cur][k][4 * ty];
            float4 a1v = *(float4*)&sA[cur][k][4 * ty + 64];
            float4 b0v = *(float4*)&sB[cur][k][4 * tx];
            float4 b1v = *(float4*)&sB[cur][k][4 * tx + 64];
            float arr[8] = {a0v.x, a0v.y, a0v.z, a0v.w, a1v.x, a1v.y, a1v.z, a1v.w};
            float brr[8] = {b0v.x, b0v.y, b0v.z, b0v.w, b1v.x, b1v.y, b1v.z, b1v.w};
#pragma unroll
            for (int i = 0; i < 8; ++i)
#pragma unroll
                for (int j = 0; j < 8; ++j) acc[i][j] += arr[i] * brr[j];
        }
        __syncthreads();
    }

#pragma unroll
    for (int i = 0; i < 8; ++i) {
        int row = s0 + ((i < 4) ? (4 * ty + i) : (64 + 4 * ty + i - 4));
        float* dst = g_Shat + ((size_t)(b * Nn + row)) * Nn + t0;
        float4 o0 = make_float4(acc[i][0], acc[i][1], acc[i][2], acc[i][3]);
        float4 o1 = make_float4(acc[i][4], acc[i][5], acc[i][6], acc[i][7]);
        *(float4*)&dst[4 * tx] = o0;
        *(float4*)&dst[4 * tx + 64] = o1;
    }
}

// ---------------- row stats: m, 1/Z ----------------
__global__ __launch_bounds__(256) void k_stats() {
    int row = blockIdx.x;
    int tid = threadIdx.x;
    const float4* p = (const float4*)(g_Shat + (size_t)row * Nn);
    float4 v = p[tid];
    float m = fmaxf(fmaxf(v.x, v.y), fmaxf(v.z, v.w));
#pragma unroll
    for (int o = 16; o > 0; o >>= 1) m = fmaxf(m, __shfl_xor_sync(0xffffffffu, m, o));
    __shared__ float smax[8];
    __shared__ float ssum[8];
    int wid = tid >> 5, lane = tid & 31;
    if (lane == 0) smax[wid] = m;
    __syncthreads();
    if (tid == 0) {
        float mm = smax[0];
#pragma unroll
        for (int i = 1; i < 8; ++i) mm = fmaxf(mm, smax[i]);
        smax[0] = mm;
    }
    __syncthreads();
    m = smax[0];
    float s = __expf(v.x - m) + __expf(v.y - m) + __expf(v.z - m) + __expf(v.w - m);
#pragma unroll
    for (int o = 16; o > 0; o >>= 1) s += __shfl_xor_sync(0xffffffffu, s, o);
    if (lane == 0) ssum[wid] = s;
    __syncthreads();
    if (tid == 0) {
        float ss = 0.f;
#pragma unroll
        for (int i = 0; i < 8; ++i) ss += ssum[i];
        g_m[row] = m;
        g_invZ[row] = 1.0f / ss;
    }
}

// ---------------- softmax write-out ----------------
__global__ __launch_bounds__(256) void k_smout(float* __restrict__ out) {
    size_t i4 = (size_t)blockIdx.x * blockDim.x + threadIdx.x;  // over 1M float4
    float4 v = ((const float4*)g_Shat)[i4];
    int row = (int)(i4 >> 8);
    float m = g_m[row], iz = g_invZ[row];
    float4 o;
    o.x = __expf(v.x - m) * iz;
    o.y = __expf(v.y - m) * iz;
    o.z = __expf(v.z - m) * iz;
    o.w = __expf(v.w - m) * iz;
    ((float4*)out)[i4] = o;
}

// ---------------- r_t = softmax(S_hat)^T @ r_s ----------------
__global__ __launch_bounds__(128) void k_rt(const float* __restrict__ rs) {
    __shared__ float s_rs[128][Rr];
    __shared__ float s_m[128];
    __shared__ float s_iz[128];
    int b = blockIdx.z;
    int t0 = blockIdx.x * 128;
    int s0 = blockIdx.y * 128;
    int tid = threadIdx.x;
#pragma unroll
    for (int i = 0; i < 16; ++i) {
        int lin = tid + 128 * i;
        int r = lin >> 4, c = lin & 15;
        s_rs[r][c] = rs[((size_t)(b * Nn + s0 + r)) * Rr + c];
    }
    s_m[tid] = g_m[b * Nn + s0 + tid];
    s_iz[tid] = g_invZ[b * Nn + s0 + tid];
    __syncthreads();

    int t = t0 + tid;
    float acc[Rr];
#pragma unroll
    for (int r = 0; r < Rr; ++r) acc[r] = 0.f;
    const float* sp = g_Shat + ((size_t)(b * Nn + s0)) * Nn + t;
#pragma unroll 4
    for (int s = 0; s < 128; ++s) {
        float w = __expf(sp[(size_t)s * Nn] - s_m[s]) * s_iz[s];
#pragma unroll
        for (int r = 0; r < Rr; ++r) acc[r] += w * s_rs[s][r];
    }
    float* rt = g_rt + (size_t)(b * Nn + t) * Rr;
#pragma unroll
    for (int q = 0; q < 4; ++q)
        red_add_f4(&rt[4 * q], make_float4(acc[4 * q], acc[4 * q + 1], acc[4 * q + 2], acc[4 * q + 3]));
}

// ---------------- psi2 aggregation (R=16, vector red) ----------------
__global__ void k_scatter16(int src_is_rt, const float* __restrict__ rext,
                            const int* __restrict__ ei) {
    int idx = blockIdx.x * blockDim.x + threadIdx.x;   // < E*4
    int e = idx >> 2;
    int q = idx & 3;
    const float* src = src_is_rt ? g_rt : rext;
    float4 v = *(const float4*)&src[(size_t)ei[e] * Rr + 4 * q];
    red_add_f4(&g_aggR[(size_t)ei[Ee + e] * Rr + 4 * q], v);
}

// ---------------- psi2 + Wm1 projection fused ----------------
__global__ __launch_bounds__(256) void k_psi2(
    int src_is_rt, const float* __restrict__ rext,
    const float* __restrict__ W2s, const float* __restrict__ W2n,
    const float* __restrict__ b2v, const float* __restrict__ Wm1,
    int use_bm1, const float* __restrict__ bm1v, int out_is_B, int step) {
    __shared__ float sr[16][17], sg[16][17], so[16][17];
    __shared__ float sWs[256], sWn[256], sWm[256];
    int tid = threadIdx.x;
    int r = tid >> 4, j = tid & 15;
    int row0 = blockIdx.x * 16;
    const float* src = src_is_rt ? g_rt : rext;
    sr[r][j] = src[(size_t)(row0 + r) * Rr + j];
    sg[r][j] = g_aggR[(size_t)(row0 + r) * Rr + j];
    sWs[tid] = W2s[tid];
    sWn[tid] = W2n[tid];
    sWm[tid] = Wm1[tid];
    __syncthreads();
    float acc = b2v[j];
#pragma unroll
    for (int k = 0; k < 16; ++k)
        acc += sr[r][k] * sWs[k * 16 + j] + sg[r][k] * sWn[k * 16 + j];
    so[r][j] = fmaxf(acc, 0.f);
    __syncthreads();
    float a2 = use_bm1 ? bm1v[j] : 0.f;
#pragma unroll
    for (int k = 0; k < 16; ++k) a2 += so[r][k] * sWm[k * 16 + j];
    float* dst = out_is_B ? g_Bt : g_As[step];
    dst[(size_t)(row0 + r) * Rr + j] = a2;
}

// ---------------- S_hat += sum_k relu(A_s[s,k]-B_t[t,k])*Wm2[k] + bm2 ----------------
__global__ __launch_bounds__(256) void k_upd(int step, const float* __restrict__ Wm2,
                                             const float* __restrict__ bm2v) {
    __shared__ float sA[16][16];
    __shared__ float swm[16];
    int b = blockIdx.z;
    int s0 = blockIdx.y * 16;
    int t0 = blockIdx.x * 256;
    int tid = threadIdx.x;
    sA[tid >> 4][tid & 15] = g_As[step][(size_t)(b * Nn + s0 + (tid >> 4)) * Rr + (tid & 15)];
    if (tid < 16) swm[tid] = Wm2[tid];
    float bb = bm2v[0];
    int t = t0 + tid;
    float Bk[16];
    const float4* bp = (const float4*)&g_Bt[(size_t)(b * Nn + t) * Rr];
    float4 b0 = bp[0], b1 = bp[1], b2 = bp[2], b3 = bp[3];
    Bk[0] = b0.x; Bk[1] = b0.y; Bk[2] = b0.z; Bk[3] = b0.w;
    Bk[4] = b1.x; Bk[5] = b1.y; Bk[6] = b1.z; Bk[7] = b1.w;
    Bk[8] = b2.x; Bk[9] = b2.y; Bk[10] = b2.z; Bk[11] = b2.w;
    Bk[12] = b3.x; Bk[13] = b3.y; Bk[14] = b3.z; Bk[15] = b3.w;
    __syncthreads();
    float* shp = g_Shat + ((size_t)(b * Nn + s0)) * Nn + t;
#pragma unroll
    for (int s = 0; s < 16; ++s) {
        float acc = bb;
#pragma unroll
        for (int k = 0; k < 16; ++k)
            acc += fmaxf(sA[s][k] - Bk[k], 0.f) * swm[k];
        shp[(size_t)s * Nn] += acc;
    }
}

// ---------------- host orchestration ----------------
extern "C" void kernel_launch(void* const* d_in, const int* in_sizes, int n_in,
                              void* d_out, int out_size) {
    const float* x_s   = (const float*)d_in[0];
    const int*   ei_s  = (const int*)d_in[1];
    const float* x_t   = (const float*)d_in[2];
    const int*   ei_t  = (const int*)d_in[3];
    const float* W1s   = (const float*)d_in[4];
    const float* W1n   = (const float*)d_in[5];
    const float* b1    = (const float*)d_in[6];
    const float* W2s   = (const float*)d_in[7];
    const float* W2n   = (const float*)d_in[8];
    const float* b2v   = (const float*)d_in[9];
    const float* Wm1   = (const float*)d_in[10];
    const float* bm1v  = (const float*)d_in[11];
    const float* Wm2   = (const float*)d_in[12];
    const float* bm2v  = (const float*)d_in[13];
    const float* rsteps = (const float*)d_in[14];
    float* out = (float*)d_out;

    // psi1
    k_zero_agg1<<<1024, 256>>>();
    k_scatter128<<<dim3(Ee * 32 / 256, 2), 256>>>(x_s, x_t, ei_s, ei_t);
    k_psi1<<<dim3(BN / 64, 2, 2), 256>>>(x_s, x_t, W1s, W1n, b1);

    // S_hat + initial stats + S_0
    k_shat<<<dim3(Nn / 128, Nn / 128, Bb), 256>>>();
    k_stats<<<BN, 256>>>();
    k_smout<<<4096, 256>>>(out);

    for (int step = 0; step < NSTEPS; ++step) {
        const float* rs = rsteps + (size_t)step * Bb * Nn * Rr;

        // o_s path -> A_s[step]
        k_zeroR<<<64, 256>>>(0);
        k_scatter16<<<Ee * 4 / 256, 256>>>(0, rs, ei_s);
        k_psi2<<<BN / 16, 256>>>(0, rs, W2s, W2n, b2v, Wm1, 1, bm1v, 0, step);

        // r_t = softmax(S_hat)^T @ r_s
        k_zeroR<<<64, 256>>>(1);
        k_rt<<<dim3(8, 8, Bb), 128>>>(rs);

        // o_t path -> B_t
        k_zeroR<<<64, 256>>>(0);
        k_scatter16<<<Ee * 4 / 256, 256>>>(1, rs, ei_t);
        k_psi2<<<BN / 16, 256>>>(1, rs, W2s, W2n, b2v, Wm1, 0, bm1v, 1, step);

        // S_hat += upd ; refresh stats
        k_upd<<<dim3(4, 64, Bb), 256>>>(step, Wm2, bm2v);
        k_stats<<<BN, 256>>>();
    }

    // S_L
    k_smout<<<4096, 256>>>(out + (size_t)Bb * Nn * Nn);
}

// round 5
// speedup vs baseline: 1.5139x; 1.0082x over previous
#include <cuda_runtime.h>

#define Bb 4
#define Nn 1024
#define BN 4096
#define Ff 128
#define Rr 16
#define Ee 65536
#define NSTEPS 2

// ---------------- scratch (device globals; no runtime allocation) ----------------
__device__ float g_agg1[2][BN * Ff];           // psi1 neighbor aggregation (s, t)
__device__ float g_h[2][BN * Ff];              // h_s, h_t
__device__ float g_Shat[(size_t)Bb * Nn * Nn]; // 16 MB logits
__device__ float g_P[(size_t)Bb * Nn * Nn];    // 16 MB exp(Shat - m) cache
__device__ float g_m[BN];                      // row max
__device__ float g_invZ[BN];                   // 1/row sum-exp
__device__ float g_rt[BN * Rr];                // r_t
__device__ float g_aggR[BN * Rr];              // psi2 aggregation scratch
__device__ float g_As[NSTEPS][BN * Rr];        // A_s = o_s@Wm1 + bm1 per step
__device__ float g_Bt[BN * Rr];                // B_t = o_t@Wm1

__device__ __forceinline__ void red_add_f4(float* p, float4 v) {
    asm volatile("red.global.add.v4.f32 [%0], {%1,%2,%3,%4};"
                 :: "l"(p), "f"(v.x), "f"(v.y), "f"(v.z), "f"(v.w) : "memory");
}

// ---------------- zero kernels ----------------
__global__ void k_zero_agg1() {
    int i = blockIdx.x * blockDim.x + threadIdx.x;      // 262144 float4
    ((float4*)g_agg1)[i] = make_float4(0.f, 0.f, 0.f, 0.f);
}

__global__ void k_zeroR(int which) {                    // 16384 float4
    float* p = which ? g_rt : g_aggR;
    int i = blockIdx.x * blockDim.x + threadIdx.x;
    ((float4*)p)[i] = make_float4(0.f, 0.f, 0.f, 0.f);
}

// ---------------- psi1 aggregation: agg[dst] += x[src] (vector red) ----------------
__global__ void k_scatter128(const float* __restrict__ xs, const float* __restrict__ xt,
                             const int* __restrict__ eis, const int* __restrict__ eit) {
    int g = blockIdx.y;
    const float* x = g ? xt : xs;
    const int* ei = g ? eit : eis;
    float* agg = g_agg1[g];
    int idx = blockIdx.x * blockDim.x + threadIdx.x;    // < E*32
    int e = idx >> 5;
    int q = idx & 31;
    int src = ei[e];
    int dst = ei[Ee + e];
    float4 v = *(const float4*)&x[(size_t)src * Ff + 4 * q];
    red_add_f4(&agg[(size_t)dst * Ff + 4 * q], v);
}

// ---------------- psi1 GEMM: h = relu(x@Ws + agg@Wn + b1) ----------------
// BM=64, BN=64, K=256 (x||agg phases); 256 threads; 4x4 micro; double-buffered
__global__ __launch_bounds__(256) void k_psi1(
    const float* __restrict__ xs, const float* __restrict__ xt,
    const float* __restrict__ Ws, const float* __restrict__ Wn,
    const float* __restrict__ bias) {
    __shared__ float sA[2][16][68];
    __shared__ float sW[2][16][68];

    int g = blockIdx.z;
    int c0 = blockIdx.y * 64;
    int row0 = blockIdx.x * 64;
    const float* x = g ? xt : xs;
    const float* agg = g_agg1[g];
    float* h = g_h[g];

    int tid = threadIdx.x;
    int tx = tid & 15, ty = tid >> 4;
    int ar_ = tid & 63, ak = (tid >> 6) * 4;
    int wr = tid >> 4, wc = 4 * (tid & 15);

    float acc[4][4];
#pragma unroll
    for (int i = 0; i < 4; ++i)
#pragma unroll
        for (int j = 0; j < 4; ++j) acc[i][j] = 0.f;

#define LOAD_A(c) (*(const float4*)&(((c) < 8) ? x : agg)[(size_t)(row0 + ar_) * Ff + (((c)*16) & 127) + ak])
#define LOAD_W(c) (*(const float4*)&(((c) < 8) ? Ws : Wn)[(size_t)((((c)*16) & 127) + wr) * Ff + c0 + wc])

    float4 va = LOAD_A(0);
    float4 vw = LOAD_W(0);
    sA[0][ak + 0][ar_] = va.x; sA[0][ak + 1][ar_] = va.y;
    sA[0][ak + 2][ar_] = va.z; sA[0][ak + 3][ar_] = va.w;
    *(float4*)&sW[0][wr][wc] = vw;
    va = LOAD_A(1);
    vw = LOAD_W(1);
    __syncthreads();

    for (int c = 0; c < 16; ++c) {
        int cur = c & 1;
        if (c < 15) {
            int nxt = cur ^ 1;
            sA[nxt][ak + 0][ar_] = va.x; sA[nxt][ak + 1][ar_] = va.y;
            sA[nxt][ak + 2][ar_] = va.z; sA[nxt][ak + 3][ar_] = va.w;
            *(float4*)&sW[nxt][wr][wc] = vw;
        }
        if (c < 14) {
            va = LOAD_A(c + 2);
            vw = LOAD_W(c + 2);
        }
#pragma unroll
        for (int k = 0; k < 16; ++k) {
            float4 a = *(float4*)&sA[cur][k][4 * ty];
            float4 w = *(float4*)&sW[cur][k][4 * tx];
            float arr[4] = {a.x, a.y, a.z, a.w};
#pragma unroll
            for (int i = 0; i < 4; ++i) {
                acc[i][0] += arr[i] * w.x; acc[i][1] += arr[i] * w.y;
                acc[i][2] += arr[i] * w.z; acc[i][3] += arr[i] * w.w;
            }
        }
        __syncthreads();
    }
#undef LOAD_A
#undef LOAD_W

    float4 bv = *(const float4*)&bias[c0 + 4 * tx];
#pragma unroll
    for (int i = 0; i < 4; ++i) {
        int row = row0 + 4 * ty + i;
        float4 o;
        o.x = fmaxf(acc[i][0] + bv.x, 0.f);
        o.y = fmaxf(acc[i][1] + bv.y, 0.f);
        o.z = fmaxf(acc[i][2] + bv.z, 0.f);
        o.w = fmaxf(acc[i][3] + bv.w, 0.f);
        *(float4*)&h[(size_t)row * Ff + c0 + 4 * tx] = o;
    }
}

// ---------------- S_hat = h_s @ h_t^T per batch ----------------
// BM=BN=128, BK=16; 256 threads; 8x8 micro; double-buffered, 1 sync/chunk
__global__ __launch_bounds__(256, 2) void k_shat() {
    __shared__ float sA[2][16][132];
    __shared__ float sB[2][16][132];

    int b = blockIdx.z;
    int t0 = blockIdx.x * 128;
    int s0 = blockIdx.y * 128;
    const float* hs = g_h[0] + (size_t)b * Nn * Ff;
    const float* ht = g_h[1] + (size_t)b * Nn * Ff;

    int tid = threadIdx.x;
    int tx = tid & 15;
    int ty = tid >> 4;
    int lr = tid & 127;
    int lk = (tid >> 7) * 4;    // 0 or 4; thread covers k = lk..lk+3 and lk+8..lk+11

    const float* pa = &hs[(size_t)(s0 + lr) * Ff + lk];
    const float* pb = &ht[(size_t)(t0 + lr) * Ff + lk];

    float acc[8][8];
#pragma unroll
    for (int i = 0; i < 8; ++i)
#pragma unroll
        for (int j = 0; j < 8; ++j) acc[i][j] = 0.f;

    float4 ra0 = *(const float4*)pa;
    float4 ra1 = *(const float4*)(pa + 8);
    float4 rb0 = *(const float4*)pb;
    float4 rb1 = *(const float4*)(pb + 8);
    sA[0][lk + 0][lr] = ra0.x; sA[0][lk + 1][lr] = ra0.y;
    sA[0][lk + 2][lr] = ra0.z; sA[0][lk + 3][lr] = ra0.w;
    sA[0][lk + 8][lr] = ra1.x; sA[0][lk + 9][lr] = ra1.y;
    sA[0][lk + 10][lr] = ra1.z; sA[0][lk + 11][lr] = ra1.w;
    sB[0][lk + 0][lr] = rb0.x; sB[0][lk + 1][lr] = rb0.y;
    sB[0][lk + 2][lr] = rb0.z; sB[0][lk + 3][lr] = rb0.w;
    sB[0][lk + 8][lr] = rb1.x; sB[0][lk + 9][lr] = rb1.y;
    sB[0][lk + 10][lr] = rb1.z; sB[0][lk + 11][lr] = rb1.w;
    ra0 = *(const float4*)(pa + 16);
    ra1 = *(const float4*)(pa + 24);
    rb0 = *(const float4*)(pb + 16);
    rb1 = *(const float4*)(pb + 24);
    __syncthreads();

    for (int c = 0; c < 8; ++c) {
        int cur = c & 1;
        if (c < 7) {
            int nxt = cur ^ 1;
            sA[nxt][lk + 0][lr] = ra0.x; sA[nxt][lk + 1][lr] = ra0.y;
            sA[nxt][lk + 2][lr] = ra0.z; sA[nxt][lk + 3][lr] = ra0.w;
            sA[nxt][lk + 8][lr] = ra1.x; sA[nxt][lk + 9][lr] = ra1.y;
            sA[nxt][lk + 10][lr] = ra1.z; sA[nxt][lk + 11][lr] = ra1.w;
            sB[nxt][lk + 0][lr] = rb0.x; sB[nxt][lk + 1][lr] = rb0.y;
            sB[nxt][lk + 2][lr] = rb0.z; sB[nxt][lk + 3][lr] = rb0.w;
            sB[nxt][lk + 8][lr] = rb1.x; sB[nxt][lk + 9][lr] = rb1.y;
            sB[nxt][lk + 10][lr] = rb1.z; sB[nxt][lk + 11][lr] = rb1.w;
        }
        if (c < 6) {
            ra0 = *(const float4*)(pa + 16 * (c + 2));
            ra1 = *(const float4*)(pa + 16 * (c + 2) + 8);
            rb0 = *(const float4*)(pb + 16 * (c + 2));
            rb1 = *(const float4*)(pb + 16 * (c + 2) + 8);
        }
#pragma unroll
        for (int k = 0; k < 16; ++k) {
            float4 a0v = *(float4*)&sA[cur][k][4 * ty];
            float4 a1v = *(float4*)&sA[cur][k][4 * ty + 64];
            float4 b0v = *(float4*)&sB[cur][k][4 * tx];
            float4 b1v = *(float4*)&sB[cur][k][4 * tx + 64];
            float arr[8] = {a0v.x, a0v.y, a0v.z, a0v.w, a1v.x, a1v.y, a1v.z, a1v.w};
            float brr[8] = {b0v.x, b0v.y, b0v.z, b0v.w, b1v.x, b1v.y, b1v.z, b1v.w};
#pragma unroll
            for (int i = 0; i < 8; ++i)
#pragma unroll
                for (int j = 0; j < 8; ++j) acc[i][j] += arr[i] * brr[j];
        }
        __syncthreads();
    }

#pragma unroll
    for (int i = 0; i < 8; ++i) {
        int row = s0 + ((i < 4) ? (4 * ty + i) : (64 + 4 * ty + i - 4));
        float* dst = g_Shat + ((size_t)(b * Nn + row)) * Nn + t0;
        float4 o0 = make_float4(acc[i][0], acc[i][1], acc[i][2], acc[i][3]);
        float4 o1 = make_float4(acc[i][4], acc[i][5], acc[i][6], acc[i][7]);
        *(float4*)&dst[4 * tx] = o0;
        *(float4*)&dst[4 * tx + 64] = o1;
    }
}

// ---------------- row stats: m, 1/Z; also caches P = exp(Shat - m) ----------------
__global__ __launch_bounds__(256) void k_stats() {
    int row = blockIdx.x;
    int tid = threadIdx.x;
    const float4* p = (const float4*)(g_Shat + (size_t)row * Nn);
    float4 v = p[tid];
    float m = fmaxf(fmaxf(v.x, v.y), fmaxf(v.z, v.w));
#pragma unroll
    for (int o = 16; o > 0; o >>= 1) m = fmaxf(m, __shfl_xor_sync(0xffffffffu, m, o));
    __shared__ float smax[8];
    __shared__ float ssum[8];
    int wid = tid >> 5, lane = tid & 31;
    if (lane == 0) smax[wid] = m;
    __syncthreads();
    if (tid == 0) {
        float mm = smax[0];
#pragma unroll
        for (int i = 1; i < 8; ++i) mm = fmaxf(mm, smax[i]);
        smax[0] = mm;
    }
    __syncthreads();
    m = smax[0];
    float4 e;
    e.x = __expf(v.x - m);
    e.y = __expf(v.y - m);
    e.z = __expf(v.z - m);
    e.w = __expf(v.w - m);
    ((float4*)(g_P + (size_t)row * Nn))[tid] = e;
    float s = e.x + e.y + e.z + e.w;
#pragma unroll
    for (int o = 16; o > 0; o >>= 1) s += __shfl_xor_sync(0xffffffffu, s, o);
    if (lane == 0) ssum[wid] = s;
    __syncthreads();
    if (tid == 0) {
        float ss = 0.f;
#pragma unroll
        for (int i = 0; i < 8; ++i) ss += ssum[i];
        g_m[row] = m;
        g_invZ[row] = 1.0f / ss;
    }
}

// ---------------- softmax write-out: out = P * invZ ----------------
__global__ __launch_bounds__(256) void k_smout(float* __restrict__ out) {
    size_t i4 = (size_t)blockIdx.x * blockDim.x + threadIdx.x;  // over 1M float4
    float4 v = ((const float4*)g_P)[i4];
    int row = (int)(i4 >> 8);
    float iz = g_invZ[row];
    float4 o;
    o.x = v.x * iz;
    o.y = v.y * iz;
    o.z = v.z * iz;
    o.w = v.w * iz;
    ((float4*)out)[i4] = o;
}

// ---------------- r_t = softmax(S_hat)^T @ r_s  (uses cached P) ----------------
__global__ __launch_bounds__(128) void k_rt(const float* __restrict__ rs) {
    __shared__ float s_rs[128][Rr];
    __shared__ float s_iz[128];
    int b = blockIdx.z;
    int t0 = blockIdx.x * 128;
    int s0 = blockIdx.y * 128;
    int tid = threadIdx.x;
#pragma unroll
    for (int i = 0; i < 16; ++i) {
        int lin = tid + 128 * i;
        int r = lin >> 4, c = lin & 15;
        s_rs[r][c] = rs[((size_t)(b * Nn + s0 + r)) * Rr + c];
    }
    s_iz[tid] = g_invZ[b * Nn + s0 + tid];
    __syncthreads();

    int t = t0 + tid;
    float acc[Rr];
#pragma unroll
    for (int r = 0; r < Rr; ++r) acc[r] = 0.f;
    const float* sp = g_P + ((size_t)(b * Nn + s0)) * Nn + t;
#pragma unroll 4
    for (int s = 0; s < 128; ++s) {
        float w = sp[(size_t)s * Nn] * s_iz[s];
#pragma unroll
        for (int r = 0; r < Rr; ++r) acc[r] += w * s_rs[s][r];
    }
    float* rt = g_rt + (size_t)(b * Nn + t) * Rr;
#pragma unroll
    for (int q = 0; q < 4; ++q)
        red_add_f4(&rt[4 * q], make_float4(acc[4 * q], acc[4 * q + 1], acc[4 * q + 2], acc[4 * q + 3]));
}

// ---------------- psi2 aggregation (R=16, vector red) ----------------
__global__ void k_scatter16(int src_is_rt, const float* __restrict__ rext,
                            const int* __restrict__ ei) {
    int idx = blockIdx.x * blockDim.x + threadIdx.x;   // < E*4
    int e = idx >> 2;
    int q = idx & 3;
    const float* src = src_is_rt ? g_rt : rext;
    float4 v = *(const float4*)&src[(size_t)ei[e] * Rr + 4 * q];
    red_add_f4(&g_aggR[(size_t)ei[Ee + e] * Rr + 4 * q], v);
}

// ---------------- psi2 + Wm1 projection fused ----------------
__global__ __launch_bounds__(256) void k_psi2(
    int src_is_rt, const float* __restrict__ rext,
    const float* __restrict__ W2s, const float* __restrict__ W2n,
    const float* __restrict__ b2v, const float* __restrict__ Wm1,
    int use_bm1, const float* __restrict__ bm1v, int out_is_B, int step) {
    __shared__ float sr[16][17], sg[16][17], so[16][17];
    __shared__ float sWs[256], sWn[256], sWm[256];
    int tid = threadIdx.x;
    int r = tid >> 4, j = tid & 15;
    int row0 = blockIdx.x * 16;
    const float* src = src_is_rt ? g_rt : rext;
    sr[r][j] = src[(size_t)(row0 + r) * Rr + j];
    sg[r][j] = g_aggR[(size_t)(row0 + r) * Rr + j];
    sWs[tid] = W2s[tid];
    sWn[tid] = W2n[tid];
    sWm[tid] = Wm1[tid];
    __syncthreads();
    float acc = b2v[j];
#pragma unroll
    for (int k = 0; k < 16; ++k)
        acc += sr[r][k] * sWs[k * 16 + j] + sg[r][k] * sWn[k * 16 + j];
    so[r][j] = fmaxf(acc, 0.f);
    __syncthreads();
    float a2 = use_bm1 ? bm1v[j] : 0.f;
#pragma unroll
    for (int k = 0; k < 16; ++k) a2 += so[r][k] * sWm[k * 16 + j];
    float* dst = out_is_B ? g_Bt : g_As[step];
    dst[(size_t)(row0 + r) * Rr + j] = a2;
}

// ---------------- S_hat += sum_k relu(A_s[s,k]-B_t[t,k])*Wm2[k] + bm2 ----------------
__global__ __launch_bounds__(256) void k_upd(int step, const float* __restrict__ Wm2,
                                             const float* __restrict__ bm2v) {
    __shared__ float sA[16][16];
    __shared__ float swm[16];
    int b = blockIdx.z;
    int s0 = blockIdx.y * 16;
    int t0 = blockIdx.x * 256;
    int tid = threadIdx.x;
    sA[tid >> 4][tid & 15] = g_As[step][(size_t)(b * Nn + s0 + (tid >> 4)) * Rr + (tid & 15)];
    if (tid < 16) swm[tid] = Wm2[tid];
    float bb = bm2v[0];
    int t = t0 + tid;
    float Bk[16];
    const float4* bp = (const float4*)&g_Bt[(size_t)(b * Nn + t) * Rr];
    float4 b0 = bp[0], b1 = bp[1], b2 = bp[2], b3 = bp[3];
    Bk[0] = b0.x; Bk[1] = b0.y; Bk[2] = b0.z; Bk[3] = b0.w;
    Bk[4] = b1.x; Bk[5] = b1.y; Bk[6] = b1.z; Bk[7] = b1.w;
    Bk[8] = b2.x; Bk[9] = b2.y; Bk[10] = b2.z; Bk[11] = b2.w;
    Bk[12] = b3.x; Bk[13] = b3.y; Bk[14] = b3.z; Bk[15] = b3.w;
    __syncthreads();
    float* shp = g_Shat + ((size_t)(b * Nn + s0)) * Nn + t;
#pragma unroll
    for (int s = 0; s < 16; ++s) {
        float acc = bb;
#pragma unroll
        for (int k = 0; k < 16; ++k)
            acc += fmaxf(sA[s][k] - Bk[k], 0.f) * swm[k];
        shp[(size_t)s * Nn] += acc;
    }
}

// ---------------- host orchestration ----------------
extern "C" void kernel_launch(void* const* d_in, const int* in_sizes, int n_in,
                              void* d_out, int out_size) {
    const float* x_s   = (const float*)d_in[0];
    const int*   ei_s  = (const int*)d_in[1];
    const float* x_t   = (const float*)d_in[2];
    const int*   ei_t  = (const int*)d_in[3];
    const float* W1s   = (const float*)d_in[4];
    const float* W1n   = (const float*)d_in[5];
    const float* b1    = (const float*)d_in[6];
    const float* W2s   = (const float*)d_in[7];
    const float* W2n   = (const float*)d_in[8];
    const float* b2v   = (const float*)d_in[9];
    const float* Wm1   = (const float*)d_in[10];
    const float* bm1v  = (const float*)d_in[11];
    const float* Wm2   = (const float*)d_in[12];
    const float* bm2v  = (const float*)d_in[13];
    const float* rsteps = (const float*)d_in[14];
    float* out = (float*)d_out;

    // psi1
    k_zero_agg1<<<1024, 256>>>();
    k_scatter128<<<dim3(Ee * 32 / 256, 2), 256>>>(x_s, x_t, ei_s, ei_t);
    k_psi1<<<dim3(BN / 64, 2, 2), 256>>>(x_s, x_t, W1s, W1n, b1);

    // S_hat + initial stats (caches P) + S_0
    k_shat<<<dim3(Nn / 128, Nn / 128, Bb), 256>>>();
    k_stats<<<BN, 256>>>();
    k_smout<<<4096, 256>>>(out);

    for (int step = 0; step < NSTEPS; ++step) {
        const float* rs = rsteps + (size_t)step * Bb * Nn * Rr;

        // o_s path -> A_s[step]
        k_zeroR<<<64, 256>>>(0);
        k_scatter16<<<Ee * 4 / 256, 256>>>(0, rs, ei_s);
        k_psi2<<<BN / 16, 256>>>(0, rs, W2s, W2n, b2v, Wm1, 1, bm1v, 0, step);

        // r_t = softmax(S_hat)^T @ r_s  (uses cached P + invZ)
        k_zeroR<<<64, 256>>>(1);
        k_rt<<<dim3(8, 8, Bb), 128>>>(rs);

        // o_t path -> B_t
        k_zeroR<<<64, 256>>>(0);
        k_scatter16<<<Ee * 4 / 256, 256>>>(1, rs, ei_t);
        k_psi2<<<BN / 16, 256>>>(1, rs, W2s, W2n, b2v, Wm1, 0, bm1v, 1, step);

        // S_hat += upd ; refresh stats (re-caches P)
        k_upd<<<dim3(4, 64, Bb), 256>>>(step, Wm2, bm2v);
        k_stats<<<BN, 256>>>();
    }

    // S_L
    k_smout<<<4096, 256>>>(out + (size_t)Bb * Nn * Nn);
}